// round 9
// baseline (speedup 1.0000x reference)
#include <cuda_runtime.h>
#include <cuda_bf16.h>

// ---------------------------------------------------------------------------
// Problem shape (fixed by setup_inputs)
// ---------------------------------------------------------------------------
#define B_ 8
#define T_ 2048
#define D_ 2048
#define M_ (B_ * T_)   // 16384 rows

__device__ float g_P[(size_t)M_ * (size_t)D_];

// ---------------------------------------------------------------------------
// mma.sync tf32 (plain sm_103 target). Raw fp32 bits as tf32 (truncation) —
// validated R7/R8, rel_err 1.764e-4.
// ---------------------------------------------------------------------------
__device__ __forceinline__ void mma_tf32(float* c, const unsigned* a, const unsigned* b) {
    asm volatile(
        "mma.sync.aligned.m16n8k8.row.col.f32.tf32.tf32.f32 "
        "{%0,%1,%2,%3}, {%4,%5,%6,%7}, {%8,%9}, {%0,%1,%2,%3};"
        : "+f"(c[0]), "+f"(c[1]), "+f"(c[2]), "+f"(c[3])
        : "r"(a[0]), "r"(a[1]), "r"(a[2]), "r"(a[3]), "r"(b[0]), "r"(b[1]));
}

__device__ __forceinline__ unsigned smem_u32(const void* p) {
    unsigned a;
    asm("{ .reg .u64 t; cvta.to.shared.u64 t, %1; cvt.u32.u64 %0, t; }" : "=r"(a) : "l"(p));
    return a;
}
__device__ __forceinline__ void cp8(unsigned dst, const void* src) {
    asm volatile("cp.async.ca.shared.global [%0], [%1], 8;" :: "r"(dst), "l"(src) : "memory");
}
__device__ __forceinline__ void cp16(unsigned dst, const void* src) {
    asm volatile("cp.async.ca.shared.global [%0], [%1], 16;" :: "r"(dst), "l"(src) : "memory");
}
#define CP_COMMIT() asm volatile("cp.async.commit_group;" ::: "memory")
#define CP_WAIT(n)  asm volatile("cp.async.wait_group %0;" :: "n"(n) : "memory")

// ---------------------------------------------------------------------------
// GEMM: P[m][n] = sum_k X[m][k]*W[n][k] + bias[n]   (TN, both K-contiguous)
// CTA 128x128, K-chunk 32, 256 thr, warp grid 2(M)x4(N), warp tile 64x32.
// acc = 64 regs/thread; __launch_bounds__(256,2) -> 2 independent CTAs/SM so
// barrier/latency shadows of one CTA are covered by the other.
//
// k-permuted fragment-major smem layout (validated R6-R8):
//   within each 8-k MMA step, fragment col c <-> physical kk {2c, 2c+1}.
//   B: one gmem float4 -> one contiguous 16B smem chunk (cp.async 16B)
//   A: one gmem float4 -> two contiguous 8B smem chunks (2x cp.async 8B)
// Consumer (per ks): A uint4 + fixup {x,z,y,w}; B uint2 direct.
// ---------------------------------------------------------------------------
#define BM 128
#define BN 128
#define KB 32
#define NCHUNK (D_ / KB)          // 64
#define A_KS 1036                 // words per 8-k A block (1024 + pad)
#define B_KS 1036                 // words per 8-k B block (1024 + pad)
#define OFF_Bw (4 * A_KS)         // 4144 words
#define STAGEW (OFF_Bw + 4 * B_KS)        // 8288 words per stage (33152 B)
#define NSTAGE 3
#define SMEM_BYTES (NSTAGE * STAGEW * 4)  // 99456 B  -> 2 CTAs/SM fit

__global__ __launch_bounds__(256, 2)
void braid_gemm_mma(const float* __restrict__ X,
                    const float* __restrict__ W,
                    const float* __restrict__ bias,
                    float* __restrict__ P) {
    extern __shared__ __align__(16) unsigned smem[];
    const unsigned sb = smem_u32(smem);
    const int tid  = threadIdx.x;
    const int lane = tid & 31;
    const int wrp  = tid >> 5;          // 0..7
    const int wm   = wrp >> 2;          // 0..1  (64 M rows)
    const int wn   = wrp & 3;           // 0..3  (32 N cols)
    const int bm   = blockIdx.y * BM;
    const int bn   = blockIdx.x * BN;

    const float* Xb = X + (size_t)bm * D_;
    const float* Wb = W + (size_t)bn * D_;

    float acc[4][4][4];
#pragma unroll
    for (int q = 0; q < 4; q++)
#pragma unroll
        for (int p = 0; p < 4; p++)
#pragma unroll
            for (int e = 0; e < 4; e++) acc[q][p][e] = 0.0f;

    // ---- async copy of chunk c into stage s (no staging registers) ----
    auto issue_chunk = [&](int c, int s) {
        const int k0 = c * KB;
        const unsigned stage = sb + (unsigned)(s * STAGEW) * 4u;
#pragma unroll
        for (int i = 0; i < 4; i++) {                    // A: 1024 float4 / 256 thr
            const int f   = tid + i * 256;
            const int row = f >> 3, c4 = f & 7;
            const int ks  = c4 >> 1;
            const int mt  = row >> 4, r = row & 7, hf = (row >> 3) & 1;
            const int c01 = (c4 & 1) * 2;
            const unsigned w0 = (unsigned)(ks * A_KS + mt * 128 + (r * 4 + c01) * 4 + hf * 2);
            const float* src = Xb + (size_t)row * D_ + k0 + c4 * 4;
            cp8(stage + w0 * 4u, src);
            cp8(stage + (w0 + 4) * 4u, src + 2);
        }
#pragma unroll
        for (int i = 0; i < 4; i++) {                    // B: 1024 float4 / 256 thr
            const int f   = tid + i * 256;
            const int row = f >> 3, c4 = f & 7;
            const int ks  = c4 >> 1;
            const int nt  = row >> 3, n = row & 7;
            const int cc  = (c4 & 1) * 2;
            const unsigned w0 = (unsigned)(OFF_Bw + ks * B_KS + nt * 64 + (n * 4 + cc) * 2);
            cp16(stage + w0 * 4u, Wb + (size_t)row * D_ + k0 + c4 * 4);
        }
        CP_COMMIT();
    };

    // ---- MMA over stage s (4 k-steps of 8) ----
    auto mma_chunk = [&](int s) {
        const unsigned* As = smem + s * STAGEW;
        const unsigned* Bs = As + OFF_Bw;
#pragma unroll
        for (int ks = 0; ks < 4; ks++) {
            unsigned a[4][4], b[4][2];
#pragma unroll
            for (int q = 0; q < 4; q++) {
                uint4 v = *reinterpret_cast<const uint4*>(
                    As + ks * A_KS + (wm * 4 + q) * 128 + lane * 4);
                a[q][0] = v.x; a[q][1] = v.z; a[q][2] = v.y; a[q][3] = v.w;  // perm fixup
            }
#pragma unroll
            for (int p = 0; p < 4; p++) {
                uint2 v = *reinterpret_cast<const uint2*>(
                    Bs + ks * B_KS + (wn * 4 + p) * 64 + lane * 2);
                b[p][0] = v.x; b[p][1] = v.y;
            }
#pragma unroll
            for (int q = 0; q < 4; q++)
#pragma unroll
                for (int p = 0; p < 4; p++)
                    mma_tf32(acc[q][p], a[q], b[p]);
        }
    };

    // ---- pipeline: 3 stages, depth-2 prefetch, one barrier per chunk.
    // Empty commit groups in the tail keep per-thread pending counts uniform
    // so CP_WAIT(1) always retires exactly chunk c.
    issue_chunk(0, 0);
    issue_chunk(1, 1);

    for (int c = 0; c < NCHUNK; c++) {
        CP_WAIT(1);                 // chunk c landed (this thread's copies)
        __syncthreads();            // all threads' copies visible; all past mma(c-1)
        if (c + 2 < NCHUNK) issue_chunk(c + 2, (c + 2) % NSTAGE);  // stage held c-1
        else CP_COMMIT();           // empty group: uniform wait semantics
        mma_chunk(c % NSTAGE);
    }

    // ---- epilogue: bias + store ----
#pragma unroll
    for (int q = 0; q < 4; q++) {
        const int gr = bm + wm * 64 + q * 16 + (lane >> 2);
#pragma unroll
        for (int p = 0; p < 4; p++) {
            const int gc = bn + wn * 32 + p * 8 + (lane & 3) * 2;
            const float2 bv = *reinterpret_cast<const float2*>(bias + gc);
            float2 o0 = make_float2(acc[q][p][0] + bv.x, acc[q][p][1] + bv.y);
            float2 o1 = make_float2(acc[q][p][2] + bv.x, acc[q][p][3] + bv.y);
            *reinterpret_cast<float2*>(&P[(size_t)gr * D_ + gc])       = o0;
            *reinterpret_cast<float2*>(&P[(size_t)(gr + 8) * D_ + gc]) = o1;
        }
    }
}

// ---------------------------------------------------------------------------
// LN epilogue (at HBM roofline — unchanged). One block per row r = b*T + t.
//   t == 0    : out = LN(x + P[r+1]/6)
//   t == T-1  : out = LN(x + P[r-1]/6)
//   else      : out = LN( LN(x + P[r-1]/6) + P[r+1]/6 )
// ---------------------------------------------------------------------------
__device__ __forceinline__ float block_reduce_sum(float v, float* sbuf) {
#pragma unroll
    for (int o = 16; o > 0; o >>= 1) v += __shfl_xor_sync(0xffffffffu, v, o);
    const int w = threadIdx.x >> 5;
    if ((threadIdx.x & 31) == 0) sbuf[w] = v;
    __syncthreads();
    if (threadIdx.x < 32) {
        float r = (threadIdx.x < 8) ? sbuf[threadIdx.x] : 0.0f;
#pragma unroll
        for (int o = 4; o > 0; o >>= 1) r += __shfl_xor_sync(0xffffffffu, r, o);
        if (threadIdx.x == 0) sbuf[8] = r;
    }
    __syncthreads();
    return sbuf[8];
}

__global__ __launch_bounds__(256)
void braid_epilogue_kernel(const float* __restrict__ X,
                           const float* __restrict__ P,
                           const float* __restrict__ gamma,
                           const float* __restrict__ beta,
                           float* __restrict__ out) {
    __shared__ float sbuf[9];
    const int r = blockIdx.x;
    const int t = r & (T_ - 1);
    const int tid = threadIdx.x;
    const float inv6 = 1.0f / 6.0f;
    const float invD = 1.0f / (float)D_;

    const size_t base = (size_t)r * D_;
    const int d0 = tid * 4, d1 = 1024 + tid * 4;

    float v[8], g[8], be[8];
    {
        const float4 ga = *reinterpret_cast<const float4*>(gamma + d0);
        const float4 gb = *reinterpret_cast<const float4*>(gamma + d1);
        const float4 ba = *reinterpret_cast<const float4*>(beta + d0);
        const float4 bb = *reinterpret_cast<const float4*>(beta + d1);
        g[0]=ga.x; g[1]=ga.y; g[2]=ga.z; g[3]=ga.w; g[4]=gb.x; g[5]=gb.y; g[6]=gb.z; g[7]=gb.w;
        be[0]=ba.x; be[1]=ba.y; be[2]=ba.z; be[3]=ba.w; be[4]=bb.x; be[5]=bb.y; be[6]=bb.z; be[7]=bb.w;
    }
    {
        const size_t nb = (t == 0) ? base + D_ : base - D_;
        const float4 xa = *reinterpret_cast<const float4*>(X + base + d0);
        const float4 xb = *reinterpret_cast<const float4*>(X + base + d1);
        const float4 pa = *reinterpret_cast<const float4*>(P + nb + d0);
        const float4 pb = *reinterpret_cast<const float4*>(P + nb + d1);
        v[0]=xa.x+inv6*pa.x; v[1]=xa.y+inv6*pa.y; v[2]=xa.z+inv6*pa.z; v[3]=xa.w+inv6*pa.w;
        v[4]=xb.x+inv6*pb.x; v[5]=xb.y+inv6*pb.y; v[6]=xb.z+inv6*pb.z; v[7]=xb.w+inv6*pb.w;
    }
    {
        float s = 0.0f;
#pragma unroll
        for (int i = 0; i < 8; i++) s += v[i];
        const float mu = block_reduce_sum(s, sbuf) * invD;
        float q = 0.0f;
#pragma unroll
        for (int i = 0; i < 8; i++) { const float c = v[i] - mu; q += c * c; }
        const float rs = rsqrtf(block_reduce_sum(q, sbuf) * invD + 1e-5f);
#pragma unroll
        for (int i = 0; i < 8; i++) v[i] = (v[i] - mu) * rs * g[i] + be[i];
    }
    if (t != 0 && t != T_ - 1) {
        const size_t nb = base + D_;
        const float4 pa = *reinterpret_cast<const float4*>(P + nb + d0);
        const float4 pb = *reinterpret_cast<const float4*>(P + nb + d1);
        v[0]+=inv6*pa.x; v[1]+=inv6*pa.y; v[2]+=inv6*pa.z; v[3]+=inv6*pa.w;
        v[4]+=inv6*pb.x; v[5]+=inv6*pb.y; v[6]+=inv6*pb.z; v[7]+=inv6*pb.w;
        float s = 0.0f;
#pragma unroll
        for (int i = 0; i < 8; i++) s += v[i];
        const float mu = block_reduce_sum(s, sbuf) * invD;
        float q = 0.0f;
#pragma unroll
        for (int i = 0; i < 8; i++) { const float c = v[i] - mu; q += c * c; }
        const float rs = rsqrtf(block_reduce_sum(q, sbuf) * invD + 1e-5f);
#pragma unroll
        for (int i = 0; i < 8; i++) v[i] = (v[i] - mu) * rs * g[i] + be[i];
    }
    *reinterpret_cast<float4*>(out + base + d0) = make_float4(v[0], v[1], v[2], v[3]);
    *reinterpret_cast<float4*>(out + base + d1) = make_float4(v[4], v[5], v[6], v[7]);
}

// ---------------------------------------------------------------------------
// Launch. Inputs: x, W1, b1, W2, b2, Wp, bp, gamma, beta.
// W1/b1/W2/b2 dead: mean(softmax(logits)) over the softmax axis == 1/6 exactly.
// ---------------------------------------------------------------------------
extern "C" void kernel_launch(void* const* d_in, const int* in_sizes, int n_in,
                              void* d_out, int out_size) {
    const float* x     = (const float*)d_in[0];
    const float* Wp    = (const float*)d_in[5];
    const float* bp    = (const float*)d_in[6];
    const float* gamma = (const float*)d_in[7];
    const float* beta  = (const float*)d_in[8];
    float* out = (float*)d_out;

    float* P;
    cudaGetSymbolAddress((void**)&P, g_P);

    cudaFuncSetAttribute(braid_gemm_mma, cudaFuncAttributeMaxDynamicSharedMemorySize, SMEM_BYTES);

    dim3 ggrid(D_ / BN, M_ / BM);   // (16, 128): x-fastest -> A-tile L2 reuse, W L2-resident
    braid_gemm_mma<<<ggrid, 256, SMEM_BYTES>>>(x, Wp, bp, P);
    braid_epilogue_kernel<<<M_, 256>>>(x, P, gamma, beta, out);
}

// round 11
// speedup vs baseline: 1.9632x; 1.9632x over previous
#include <cuda_runtime.h>
#include <cuda_fp16.h>

// ---------------------------------------------------------------------------
// Problem shape (fixed by setup_inputs)
// ---------------------------------------------------------------------------
#define B_ 8
#define T_ 2048
#define D_ 2048
#define M_ (B_ * T_)   // 16384 rows

__device__ float g_P[(size_t)M_ * (size_t)D_];

// ---------------------------------------------------------------------------
// fp16 helpers. fp16 mantissa (11 bit) == tf32 mantissa -> tf32-class accuracy
// (R5 measured 6.8e-5 with rna tf32), but m16n8k16 does 2x MACs per HMMA.
// ---------------------------------------------------------------------------
__device__ __forceinline__ unsigned pack_f16(float lo, float hi) {
    unsigned r;
    asm("cvt.rn.f16x2.f32 %0, %1, %2;" : "=r"(r) : "f"(hi), "f"(lo));  // 1st src = upper
    return r;
}
__device__ __forceinline__ void mma_f16(float* c, const unsigned* a, const unsigned* b) {
    asm volatile(
        "mma.sync.aligned.m16n8k16.row.col.f32.f16.f16.f32 "
        "{%0,%1,%2,%3}, {%4,%5,%6,%7}, {%8,%9}, {%0,%1,%2,%3};"
        : "+f"(c[0]), "+f"(c[1]), "+f"(c[2]), "+f"(c[3])
        : "r"(a[0]), "r"(a[1]), "r"(a[2]), "r"(a[3]), "r"(b[0]), "r"(b[1]));
}

// ---------------------------------------------------------------------------
// GEMM: P[m][n] = sum_k X[m][k]*W[n][k] + bias[n]   (TN, both K-contiguous)
// CTA 128x256, K-chunk 32 (= 2 MMA k-steps of 16), 256 thr, 2x4 warps, 64x64.
// R5 schedule (best measured): reg-staged producer, double buffer, 1 barrier/chunk.
//
// k-permutation per 16-k step: fragment k-pair kp=c <-> phys pair 2c,
// kp=c+4 <-> phys pair 2c+1 (c = 0..3). A and B permute identically; k is a
// reduction axis, so the result is exact.
// SMEM per 16-k step, fragment-major:
//   A mtile(16 rows): lane word4 = [a0,a2,a1,a3] -> consumer uint4 + {x,z,y,w} fixup;
//     producer: one gmem float4 (4 consecutive k) -> one uint2 STS.64.
//   B ntile(8 cols):  lane word2 = [b0,b1] -> consumer uint2 direct;
//     producer: one gmem float4 -> one uint2 STS.64.
// ---------------------------------------------------------------------------
#define BM 128
#define BN 256
#define KB 32
#define NCHUNK (D_ / KB)          // 64
#define A_KS 1032                 // words per 16-k A block (8 mtiles*128 + 8 pad)
#define B_KS 2056                 // words per 16-k B block (32 ntiles*64 + 8 pad)
#define OFF_Bw (2 * A_KS)         // 2064 words
#define STAGEW (OFF_Bw + 2 * B_KS)       // 6176 words (24704 B) per stage
#define SMEM_BYTES (2 * STAGEW * 4)      // 49408 B

__global__ __launch_bounds__(256, 1)
void braid_gemm_mma(const float* __restrict__ X,
                    const float* __restrict__ W,
                    const float* __restrict__ bias,
                    float* __restrict__ P) {
    extern __shared__ __align__(16) unsigned smem[];
    const int tid  = threadIdx.x;
    const int lane = tid & 31;
    const int wrp  = tid >> 5;          // 0..7
    const int wm   = wrp >> 2;          // 0..1  (64 M rows)
    const int wn   = wrp & 3;           // 0..3  (64 N cols)
    const int bm   = blockIdx.y * BM;
    const int bn   = blockIdx.x * BN;

    const float* Xb = X + (size_t)bm * D_;
    const float* Wb = W + (size_t)bn * D_;

    float acc[4][8][4];
#pragma unroll
    for (int q = 0; q < 4; q++)
#pragma unroll
        for (int p = 0; p < 8; p++)
#pragma unroll
            for (int e = 0; e < 4; e++) acc[q][p][e] = 0.0f;

    float4 ar[4], br[8];

    // ---- gmem -> regs (coalesced float4) ----
    auto ldg_chunk = [&](int c) {
        const int k0 = c * KB;
#pragma unroll
        for (int i = 0; i < 4; i++) {                    // A: 1024 float4
            const int f = tid + i * 256;
            ar[i] = *reinterpret_cast<const float4*>(
                Xb + (size_t)(f >> 3) * D_ + k0 + (f & 7) * 4);
        }
#pragma unroll
        for (int i = 0; i < 8; i++) {                    // B: 2048 float4
            const int f = tid + i * 256;
            br[i] = *reinterpret_cast<const float4*>(
                Wb + (size_t)(f >> 3) * D_ + k0 + (f & 7) * 4);
        }
    };

    // ---- regs -> smem (fp16 convert, permuted fragment-major, STS.64 only) ----
    auto sts_chunk = [&](int s) {
        unsigned* As = smem + s * STAGEW;
        unsigned* Bs = As + OFF_Bw;
#pragma unroll
        for (int i = 0; i < 4; i++) {
            const int f   = tid + i * 256;
            const int row = f >> 3, c4 = f & 7;
            const int ks  = c4 >> 2, c = c4 & 3;
            const int mt  = row >> 4, r = row & 7, hf = (row >> 3) & 1;
            const int w0  = ks * A_KS + mt * 128 + (r * 4 + c) * 4 + hf * 2;
            *reinterpret_cast<uint2*>(As + w0) =
                make_uint2(pack_f16(ar[i].x, ar[i].y), pack_f16(ar[i].z, ar[i].w));
        }
#pragma unroll
        for (int i = 0; i < 8; i++) {
            const int f   = tid + i * 256;
            const int row = f >> 3, c4 = f & 7;
            const int ks  = c4 >> 2, c = c4 & 3;
            const int nt  = row >> 3, n = row & 7;
            const int w0  = ks * B_KS + nt * 64 + (n * 4 + c) * 2;
            *reinterpret_cast<uint2*>(Bs + w0) =
                make_uint2(pack_f16(br[i].x, br[i].y), pack_f16(br[i].z, br[i].w));
        }
    };

    // ---- MMA over stage s (2 k-steps of 16) ----
    auto mma_chunk = [&](int s) {
        const unsigned* As = smem + s * STAGEW;
        const unsigned* Bs = As + OFF_Bw;
#pragma unroll
        for (int ks = 0; ks < 2; ks++) {
            unsigned a[4][4], b[8][2];
#pragma unroll
            for (int q = 0; q < 4; q++) {
                uint4 v = *reinterpret_cast<const uint4*>(
                    As + ks * A_KS + (wm * 4 + q) * 128 + lane * 4);
                a[q][0] = v.x; a[q][1] = v.z; a[q][2] = v.y; a[q][3] = v.w;  // [a0,a2,a1,a3]
            }
#pragma unroll
            for (int p = 0; p < 8; p++) {
                uint2 v = *reinterpret_cast<const uint2*>(
                    Bs + ks * B_KS + (wn * 8 + p) * 64 + lane * 2);
                b[p][0] = v.x; b[p][1] = v.y;
            }
#pragma unroll
            for (int q = 0; q < 4; q++)
#pragma unroll
                for (int p = 0; p < 8; p++)
                    mma_f16(acc[q][p], a[q], b[p]);
        }
    };

    // ---- R5 schedule: double buffer, one barrier per chunk ----
    ldg_chunk(0);
    sts_chunk(0);
    __syncthreads();

    for (int c = 0; c < NCHUNK; c++) {
        const int s = c & 1;
        const bool more = (c + 1 < NCHUNK);
        if (more) ldg_chunk(c + 1);
        mma_chunk(s);
        if (more) {
            sts_chunk(s ^ 1);       // stage held chunk c-1: consumed before last barrier
            __syncthreads();
        }
    }

    // ---- epilogue: bias + store ----
#pragma unroll
    for (int q = 0; q < 4; q++) {
        const int gr = bm + wm * 64 + q * 16 + (lane >> 2);
#pragma unroll
        for (int p = 0; p < 8; p++) {
            const int gc = bn + wn * 64 + p * 8 + (lane & 3) * 2;
            const float2 bv = *reinterpret_cast<const float2*>(bias + gc);
            float2 o0 = make_float2(acc[q][p][0] + bv.x, acc[q][p][1] + bv.y);
            float2 o1 = make_float2(acc[q][p][2] + bv.x, acc[q][p][3] + bv.y);
            *reinterpret_cast<float2*>(&P[(size_t)gr * D_ + gc])       = o0;
            *reinterpret_cast<float2*>(&P[(size_t)(gr + 8) * D_ + gc]) = o1;
        }
    }
}

// ---------------------------------------------------------------------------
// LN epilogue (at HBM roofline — unchanged). One block per row r = b*T + t.
//   t == 0    : out = LN(x + P[r+1]/6)
//   t == T-1  : out = LN(x + P[r-1]/6)
//   else      : out = LN( LN(x + P[r-1]/6) + P[r+1]/6 )
// ---------------------------------------------------------------------------
__device__ __forceinline__ float block_reduce_sum(float v, float* sbuf) {
#pragma unroll
    for (int o = 16; o > 0; o >>= 1) v += __shfl_xor_sync(0xffffffffu, v, o);
    const int w = threadIdx.x >> 5;
    if ((threadIdx.x & 31) == 0) sbuf[w] = v;
    __syncthreads();
    if (threadIdx.x < 32) {
        float r = (threadIdx.x < 8) ? sbuf[threadIdx.x] : 0.0f;
#pragma unroll
        for (int o = 4; o > 0; o >>= 1) r += __shfl_xor_sync(0xffffffffu, r, o);
        if (threadIdx.x == 0) sbuf[8] = r;
    }
    __syncthreads();
    return sbuf[8];
}

__global__ __launch_bounds__(256)
void braid_epilogue_kernel(const float* __restrict__ X,
                           const float* __restrict__ P,
                           const float* __restrict__ gamma,
                           const float* __restrict__ beta,
                           float* __restrict__ out) {
    __shared__ float sbuf[9];
    const int r = blockIdx.x;
    const int t = r & (T_ - 1);
    const int tid = threadIdx.x;
    const float inv6 = 1.0f / 6.0f;
    const float invD = 1.0f / (float)D_;

    const size_t base = (size_t)r * D_;
    const int d0 = tid * 4, d1 = 1024 + tid * 4;

    float v[8], g[8], be[8];
    {
        const float4 ga = *reinterpret_cast<const float4*>(gamma + d0);
        const float4 gb = *reinterpret_cast<const float4*>(gamma + d1);
        const float4 ba = *reinterpret_cast<const float4*>(beta + d0);
        const float4 bb = *reinterpret_cast<const float4*>(beta + d1);
        g[0]=ga.x; g[1]=ga.y; g[2]=ga.z; g[3]=ga.w; g[4]=gb.x; g[5]=gb.y; g[6]=gb.z; g[7]=gb.w;
        be[0]=ba.x; be[1]=ba.y; be[2]=ba.z; be[3]=ba.w; be[4]=bb.x; be[5]=bb.y; be[6]=bb.z; be[7]=bb.w;
    }
    {
        const size_t nb = (t == 0) ? base + D_ : base - D_;
        const float4 xa = *reinterpret_cast<const float4*>(X + base + d0);
        const float4 xb = *reinterpret_cast<const float4*>(X + base + d1);
        const float4 pa = *reinterpret_cast<const float4*>(P + nb + d0);
        const float4 pb = *reinterpret_cast<const float4*>(P + nb + d1);
        v[0]=xa.x+inv6*pa.x; v[1]=xa.y+inv6*pa.y; v[2]=xa.z+inv6*pa.z; v[3]=xa.w+inv6*pa.w;
        v[4]=xb.x+inv6*pb.x; v[5]=xb.y+inv6*pb.y; v[6]=xb.z+inv6*pb.z; v[7]=xb.w+inv6*pb.w;
    }
    {
        float s = 0.0f;
#pragma unroll
        for (int i = 0; i < 8; i++) s += v[i];
        const float mu = block_reduce_sum(s, sbuf) * invD;
        float q = 0.0f;
#pragma unroll
        for (int i = 0; i < 8; i++) { const float c = v[i] - mu; q += c * c; }
        const float rs = rsqrtf(block_reduce_sum(q, sbuf) * invD + 1e-5f);
#pragma unroll
        for (int i = 0; i < 8; i++) v[i] = (v[i] - mu) * rs * g[i] + be[i];
    }
    if (t != 0 && t != T_ - 1) {
        const size_t nb = base + D_;
        const float4 pa = *reinterpret_cast<const float4*>(P + nb + d0);
        const float4 pb = *reinterpret_cast<const float4*>(P + nb + d1);
        v[0]+=inv6*pa.x; v[1]+=inv6*pa.y; v[2]+=inv6*pa.z; v[3]+=inv6*pa.w;
        v[4]+=inv6*pb.x; v[5]+=inv6*pb.y; v[6]+=inv6*pb.z; v[7]+=inv6*pb.w;
        float s = 0.0f;
#pragma unroll
        for (int i = 0; i < 8; i++) s += v[i];
        const float mu = block_reduce_sum(s, sbuf) * invD;
        float q = 0.0f;
#pragma unroll
        for (int i = 0; i < 8; i++) { const float c = v[i] - mu; q += c * c; }
        const float rs = rsqrtf(block_reduce_sum(q, sbuf) * invD + 1e-5f);
#pragma unroll
        for (int i = 0; i < 8; i++) v[i] = (v[i] - mu) * rs * g[i] + be[i];
    }
    *reinterpret_cast<float4*>(out + base + d0) = make_float4(v[0], v[1], v[2], v[3]);
    *reinterpret_cast<float4*>(out + base + d1) = make_float4(v[4], v[5], v[6], v[7]);
}

// ---------------------------------------------------------------------------
// Launch. Inputs: x, W1, b1, W2, b2, Wp, bp, gamma, beta.
// W1/b1/W2/b2 dead: mean(softmax(logits)) over the softmax axis == 1/6 exactly.
// ---------------------------------------------------------------------------
extern "C" void kernel_launch(void* const* d_in, const int* in_sizes, int n_in,
                              void* d_out, int out_size) {
    const float* x     = (const float*)d_in[0];
    const float* Wp    = (const float*)d_in[5];
    const float* bp    = (const float*)d_in[6];
    const float* gamma = (const float*)d_in[7];
    const float* beta  = (const float*)d_in[8];
    float* out = (float*)d_out;

    float* P;
    cudaGetSymbolAddress((void**)&P, g_P);

    cudaFuncSetAttribute(braid_gemm_mma, cudaFuncAttributeMaxDynamicSharedMemorySize, SMEM_BYTES);

    dim3 ggrid(D_ / BN, M_ / BM);   // (8, 128): x-fastest -> A-tile L2 reuse, W L2-resident
    braid_gemm_mma<<<ggrid, 256, SMEM_BYTES>>>(x, Wp, bp, P);
    braid_epilogue_kernel<<<M_, 256>>>(x, P, gamma, beta, out);
}